// round 16
// baseline (speedup 1.0000x reference)
#include <cuda_runtime.h>
#include <cuda_bf16.h>
#include <cstdint>

#define NN 8192
#define CF 256          // H * OUT_F
#define NHEADS 4
#define CHUNKS 8
#define JTILE 32
#define JCHUNK (NN / CHUNKS)          // 1024
#define NT (JCHUNK / JTILE)           // 32 tiles per chunk
#define RPB 64                        // i-rows per block
#define ATHREADS 512
#define NBUF 3
#define TILE_BYTES (JTILE * CF * 4)     // 32768 (fp32, permuted)
#define STAT_BYTES (JTILE * NHEADS * 8) // 1024

// ---------------- scratch (device globals: allocation-free) ----------------
__device__ float  g_support[(size_t)NN * CF];       // fp32 (stats input)
__device__ float  g_support_perm[(size_t)NN * CF];  // fp32, column-permuted (attn)
__device__ float2 g_statJ[NN * NHEADS];             // {e^f1, e^.2f1} per (j,h)
__device__ float2 g_statI[NN * NHEADS];             // {e^f2, e^.2f2} per (i,h)
__device__ float  g_pnum[(size_t)CHUNKS * NN * CF]; // partial numerators
__device__ float  g_pden[(size_t)CHUNKS * NN * NHEADS];

__device__ __forceinline__ unsigned smem_u32(const void* p) {
    return (unsigned)__cvta_generic_to_shared(p);
}

__device__ __forceinline__ void mbar_wait(unsigned mb, unsigned par) {
    unsigned done;
    asm volatile(
        "{\n\t.reg .pred p;\n\t"
        "mbarrier.try_wait.parity.acquire.cta.shared::cta.b64 p, [%1], %2;\n\t"
        "selp.b32 %0, 1, 0, p;\n\t}"
        : "=r"(done) : "r"(mb), "r"(par) : "memory");
    if (!done) {
        asm volatile(
            "{\n\t.reg .pred P1;\n\t"
            "WL_%=:\n\t"
            "mbarrier.try_wait.parity.acquire.cta.shared::cta.b64 P1, [%0], %1, 0x989680;\n\t"
            "@P1 bra.uni WD_%=;\n\t"
            "bra.uni WL_%=;\n\t"
            "WD_%=:\n\t}"
            :: "r"(mb), "r"(par) : "memory");
    }
}

// ------------- dual SGEMM: support = A@W (+perm copy), out = A@P^T + biases -
// A [8192,256]; W [256,256] row-major (k-major); P [256,256] (row n, col k).
__global__ __launch_bounds__(256) void dual_gemm_kernel(
    const float* __restrict__ A, const float* __restrict__ W,
    const float* __restrict__ P, float* __restrict__ C,
    const float* __restrict__ bias1, const float* __restrict__ bias2)
{
    __shared__ float As[16][68];
    __shared__ float Bs1[16][68];
    __shared__ float Bs2[16][68];
    int tid = threadIdx.x;
    int tx = tid & 15, ty = tid >> 4;
    int m0 = blockIdx.y * 64, n0 = blockIdx.x * 64;
    float acc1[4][4] = {};
    float acc2[4][4] = {};

    for (int kb = 0; kb < 256; kb += 16) {
        {   // A tile [64 x 16] -> As[k][m]
            int m = tid >> 2, kq = tid & 3;
            float4 a4 = *(const float4*)(A + (size_t)(m0 + m) * 256 + kb + kq * 4);
            As[kq * 4 + 0][m] = a4.x; As[kq * 4 + 1][m] = a4.y;
            As[kq * 4 + 2][m] = a4.z; As[kq * 4 + 3][m] = a4.w;
        }
        {   // W tile: Bs1[k][n]
            int k = tid >> 4, nq = tid & 15;
            *(float4*)&Bs1[k][nq * 4] =
                *(const float4*)(W + (size_t)(kb + k) * CF + n0 + nq * 4);
        }
        {   // P tile (transposed stage): Bs2[k][n] = P[n][k]
            int n = tid >> 2, kq = tid & 3;
            float4 b4 = *(const float4*)(P + (size_t)(n0 + n) * 256 + kb + kq * 4);
            Bs2[kq * 4 + 0][n] = b4.x; Bs2[kq * 4 + 1][n] = b4.y;
            Bs2[kq * 4 + 2][n] = b4.z; Bs2[kq * 4 + 3][n] = b4.w;
        }
        __syncthreads();
        #pragma unroll
        for (int k = 0; k < 16; ++k) {
            float4 ra  = *(const float4*)&As[k][ty * 4];
            float4 rb1 = *(const float4*)&Bs1[k][tx * 4];
            float4 rb2 = *(const float4*)&Bs2[k][tx * 4];
            float a[4] = {ra.x, ra.y, ra.z, ra.w};
            float b1[4] = {rb1.x, rb1.y, rb1.z, rb1.w};
            float b2[4] = {rb2.x, rb2.y, rb2.z, rb2.w};
            #pragma unroll
            for (int ii = 0; ii < 4; ++ii)
                #pragma unroll
                for (int jj = 0; jj < 4; ++jj) {
                    acc1[ii][jj] += a[ii] * b1[jj];
                    acc2[ii][jj] += a[ii] * b2[jj];
                }
        }
        __syncthreads();
    }

    #pragma unroll
    for (int ii = 0; ii < 4; ++ii) {
        int row = m0 + ty * 4 + ii;
        #pragma unroll
        for (int jj = 0; jj < 4; ++jj) {
            int col = n0 + tx * 4 + jj;
            float v = acc1[ii][jj];
            g_support[(size_t)row * CF + col] = v;
            // permuted: lane (col>>3) owns 8 cols; first 4 at lane*4 in
            // [0,128), last 4 at 128 + lane*4 (conflict-light LDS.128 pairs).
            int g = col >> 3, half = (col >> 2) & 1, q = col & 3;
            int p = half * 128 + g * 4 + q;
            g_support_perm[(size_t)row * CF + p] = v;
            C[(size_t)row * CF + col] = acc2[ii][jj] + bias1[col] + bias2[col];
        }
    }
}

// ------------- per-node head scalars: exponentials only ---------------------
__global__ __launch_bounds__(256) void stats_kernel(
    const float* __restrict__ wu, const float* __restrict__ wv)
{
    int t = blockIdx.x * blockDim.x + threadIdx.x;   // 0 .. 32767
    int n = t >> 2, h = t & 3;
    const float* srow = g_support + (size_t)n * CF + h * 64;
    float s1 = 0.f, s2 = 0.f;
    #pragma unroll 8
    for (int o = 0; o < 64; ++o) {
        float sv = srow[o];
        s1 += sv * wu[h * 64 + o];
        s2 += sv * wv[h * 64 + o];
    }
    g_statJ[n * NHEADS + h] = make_float2(__expf(s1), __expf(0.2f * s1));
    g_statI[n * NHEADS + h] = make_float2(__expf(s2), __expf(0.2f * s2));
}

// -------------------------- sparse attention (partial) ---------------------
// grid (128, 8): blockIdx.x = i-block (64 rows), blockIdx.y = j-chunk (1024 j)
// 512 thr = 16 warps; warp w owns rows w*4..w*4+3; lane owns cols lane*8..+7.
// 3-buffer bulk-TMA pipeline (R11 structure, measured good) with fp32
// permuted tiles: per edge = 2x LDS.128 + 4x FFMA2, no bf16 unpack.
__global__ __launch_bounds__(ATHREADS, 2) void attn_partial(
    const float* __restrict__ adj)
{
    extern __shared__ char smraw[];
    float*  sS    = (float*)smraw;                          // [3][32][256] fp32
    float2* sstat = (float2*)(smraw + NBUF * TILE_BYTES);   // [3][32][4]
    __shared__ unsigned long long mbars[NBUF];

    int tid = threadIdx.x, warp = tid >> 5, lane = tid & 31;
    int i0 = blockIdx.x * RPB;
    int chunk = blockIdx.y;
    int j0 = chunk * JCHUNK;
    int h = lane >> 3;
    int ibase = i0 + warp * 4;

    if (tid == 0) {
        #pragma unroll
        for (int b = 0; b < NBUF; ++b)
            asm volatile("mbarrier.init.shared.b64 [%0], 1;"
                         :: "r"(smem_u32(&mbars[b])) : "memory");
    }
    __syncthreads();

    auto issue_tile = [&](int t, int b) {   // tid==0 only
        unsigned mb = smem_u32(&mbars[b]);
        asm volatile("mbarrier.arrive.expect_tx.shared.b64 _, [%0], %1;"
                     :: "r"(mb), "r"(TILE_BYTES + STAT_BYTES) : "memory");
        const char* srcS = (const char*)(g_support_perm + (size_t)(j0 + t * JTILE) * CF);
        unsigned dstS = smem_u32(sS + (size_t)b * JTILE * CF);
        asm volatile(
            "cp.async.bulk.shared::cta.global.mbarrier::complete_tx::bytes "
            "[%0], [%1], %2, [%3];"
            :: "r"(dstS), "l"(srcS), "r"(TILE_BYTES), "r"(mb) : "memory");
        const char* srcT = (const char*)(g_statJ + (size_t)(j0 + t * JTILE) * NHEADS);
        unsigned dstT = smem_u32(sstat + b * JTILE * NHEADS);
        asm volatile(
            "cp.async.bulk.shared::cta.global.mbarrier::complete_tx::bytes "
            "[%0], [%1], %2, [%3];"
            :: "r"(dstT), "l"(srcT), "r"(STAT_BYTES), "r"(mb) : "memory");
    };

    float br[4], b5r[4];
    #pragma unroll
    for (int rr = 0; rr < 4; ++rr) {
        float2 si = g_statI[(size_t)(ibase + rr) * NHEADS + h];
        br[rr] = si.x; b5r[rr] = si.y;
    }

    unsigned long long accp[4][4] = {};   // packed f32x2 accumulators
    float den[4] = {0.f, 0.f, 0.f, 0.f};

    float av[4];
    #pragma unroll
    for (int rr = 0; rr < 4; ++rr)
        av[rr] = adj[(size_t)(ibase + rr) * NN + j0 + lane];

    if (tid == 0) {
        issue_tile(0, 0);
        issue_tile(1, 1);
        issue_tile(2, 2);
    }

    int b = 0, par = 0;
    for (int jt = 0; jt < NT; ++jt) {
        // wait for tile jt (acquire orders subsequent LDS after TMA writes)
        mbar_wait(smem_u32(&mbars[b]), (unsigned)par);

        unsigned m[4];
        #pragma unroll
        for (int rr = 0; rr < 4; ++rr)
            m[rr] = __ballot_sync(0xffffffffu, av[rr] != 0.0f);

        if (jt + 1 < NT) {
            #pragma unroll
            for (int rr = 0; rr < 4; ++rr)
                av[rr] = adj[(size_t)(ibase + rr) * NN + j0 + (jt + 1) * JTILE + lane];
        }

        const float*  tile = sS + (size_t)b * JTILE * CF;
        const float2* stt  = sstat + b * JTILE * NHEADS;

        #pragma unroll
        for (int rr = 0; rr < 4; ++rr) {
            unsigned mask = m[rr];
            while (mask) {
                int j = __ffs(mask) - 1;
                mask &= mask - 1;
                float2 st = stt[j * NHEADS + h];            // {e^f1, e^.2f1}
                // exp(leaky_relu(f1+f2)) == max(e^f1 e^f2, e^.2f1 e^.2f2)
                float e = fmaxf(st.x * br[rr], st.y * b5r[rr]);
                den[rr] += e;
                unsigned long long e2;
                asm("mov.b64 %0, {%1, %1};" : "=l"(e2) : "f"(e));
                const ulonglong2* sp =
                    (const ulonglong2*)(tile + (size_t)j * CF) + lane; // 16B @ lane*16
                ulonglong2 w0 = sp[0];       // orig cols lane*8 .. +3
                ulonglong2 w1 = sp[32];      // +512B: cols lane*8+4 .. +7
                asm("fma.rn.f32x2 %0, %1, %2, %0;" : "+l"(accp[rr][0]) : "l"(w0.x), "l"(e2));
                asm("fma.rn.f32x2 %0, %1, %2, %0;" : "+l"(accp[rr][1]) : "l"(w0.y), "l"(e2));
                asm("fma.rn.f32x2 %0, %1, %2, %0;" : "+l"(accp[rr][2]) : "l"(w1.x), "l"(e2));
                asm("fma.rn.f32x2 %0, %1, %2, %0;" : "+l"(accp[rr][3]) : "l"(w1.y), "l"(e2));
            }
        }

        __syncthreads();   // all warps done with tile jt; buffer b reusable
        if (tid == 0 && jt + 3 < NT) issue_tile(jt + 3, b);
        if (++b == NBUF) { b = 0; par ^= 1; }
    }

    // write partials
    #pragma unroll
    for (int rr = 0; rr < 4; ++rr) {
        int i = ibase + rr;
        float o[8];
        #pragma unroll
        for (int k = 0; k < 4; ++k) {
            unsigned lo, hi;
            asm("mov.b64 {%0, %1}, %2;" : "=r"(lo), "=r"(hi) : "l"(accp[rr][k]));
            o[k * 2]     = __uint_as_float(lo);
            o[k * 2 + 1] = __uint_as_float(hi);
        }
        float* pn = g_pnum + ((size_t)chunk * NN + i) * CF + (lane << 3);
        *(float4*)pn       = make_float4(o[0], o[1], o[2], o[3]);
        *(float4*)(pn + 4) = make_float4(o[4], o[5], o[6], o[7]);
        if ((lane & 7) == 0)
            g_pden[((size_t)chunk * NN + i) * NHEADS + h] = den[rr];
    }
}

// -------------------- combine partials: out += num/den ---------------------
__global__ __launch_bounds__(256) void combine_kernel(float* __restrict__ out)
{
    int i = blockIdx.x;
    int c = threadIdx.x;
    int h = c >> 6;
    float s = 0.f, d = 0.f;
    #pragma unroll
    for (int k = 0; k < CHUNKS; ++k) {
        s += g_pnum[((size_t)k * NN + i) * CF + c];
        d += g_pden[((size_t)k * NN + i) * NHEADS + h];
    }
    out[(size_t)i * CF + c] += s / d;
}

// ------------------------------- launch ------------------------------------
extern "C" void kernel_launch(void* const* d_in, const int* in_sizes, int n_in,
                              void* d_out, int out_size)
{
    const float* inputs = (const float*)d_in[0];
    const float* adj    = (const float*)d_in[1];
    const float* weight = (const float*)d_in[2];
    const float* wu     = (const float*)d_in[3];
    const float* wv     = (const float*)d_in[4];
    const float* bias   = (const float*)d_in[5];
    const float* projw  = (const float*)d_in[6];
    const float* projb  = (const float*)d_in[7];
    float* out = (float*)d_out;

    const int ASMEM = NBUF * TILE_BYTES + NBUF * STAT_BYTES;  // 101376
    cudaFuncSetAttribute(attn_partial,
                         cudaFuncAttributeMaxDynamicSharedMemorySize, ASMEM);

    dim3 gemm_grid(CF / 64, NN / 64);   // (4, 128)

    // support = inputs @ weight (+perm copy); out = inputs @ proj_w.T + biases
    dual_gemm_kernel<<<gemm_grid, 256>>>(inputs, weight, projw, out,
                                         bias, projb);
    // per-node head scalars + exponentials
    stats_kernel<<<NN * NHEADS / 256, 256>>>(wu, wv);
    // partial attention over j-chunks
    attn_partial<<<dim3(NN / RPB, CHUNKS), ATHREADS, ASMEM>>>(adj);
    // out += num/den
    combine_kernel<<<NN, 256>>>(out);
}

// round 17
// speedup vs baseline: 1.4308x; 1.4308x over previous
#include <cuda_runtime.h>
#include <cuda_bf16.h>
#include <cstdint>

#define NN 8192
#define CF 256          // H * OUT_F
#define NHEADS 4
#define CHUNKS 8
#define JTILE 64                      // staged tile (2 ballot groups of 32)
#define JCHUNK (NN / CHUNKS)          // 1024
#define NT (JCHUNK / JTILE)           // 16 tiles per chunk
#define RPB 64                        // i-rows per block
#define ATHREADS 512
#define NBUF 3
#define TILE_BYTES (JTILE * CF * 2)     // 32768 (bf16)
#define STAT_BYTES (JTILE * NHEADS * 8) // 2048

// ---------------- scratch (device globals: allocation-free) ----------------
__device__ float          g_support[(size_t)NN * CF];     // fp32 (stats input)
__device__ __nv_bfloat16  g_support_bf[(size_t)NN * CF];  // bf16 (attn tiles)
__device__ float2 g_statJ[NN * NHEADS];             // {e^f1, e^.2f1} per (j,h)
__device__ float2 g_statI[NN * NHEADS];             // {e^f2, e^.2f2} per (i,h)
__device__ float  g_pnum[(size_t)CHUNKS * NN * CF]; // partial numerators
__device__ float  g_pden[(size_t)CHUNKS * NN * NHEADS];

__device__ __forceinline__ unsigned smem_u32(const void* p) {
    return (unsigned)__cvta_generic_to_shared(p);
}

__device__ __forceinline__ void mbar_wait(unsigned mb, unsigned par) {
    unsigned done;
    asm volatile(
        "{\n\t.reg .pred p;\n\t"
        "mbarrier.try_wait.parity.acquire.cta.shared::cta.b64 p, [%1], %2;\n\t"
        "selp.b32 %0, 1, 0, p;\n\t}"
        : "=r"(done) : "r"(mb), "r"(par) : "memory");
    if (!done) {
        asm volatile(
            "{\n\t.reg .pred P1;\n\t"
            "WL_%=:\n\t"
            "mbarrier.try_wait.parity.acquire.cta.shared::cta.b64 P1, [%0], %1, 0x989680;\n\t"
            "@P1 bra.uni WD_%=;\n\t"
            "bra.uni WL_%=;\n\t"
            "WD_%=:\n\t}"
            :: "r"(mb), "r"(par) : "memory");
    }
}

// ------------- dual SGEMM: support = A@W (+bf16), out = A@P^T + biases -----
// A [8192,256]; W [256,256] row-major (k-major); P [256,256] (row n, col k).
__global__ __launch_bounds__(256) void dual_gemm_kernel(
    const float* __restrict__ A, const float* __restrict__ W,
    const float* __restrict__ P, float* __restrict__ C,
    const float* __restrict__ bias1, const float* __restrict__ bias2)
{
    __shared__ float As[16][68];
    __shared__ float Bs1[16][68];
    __shared__ float Bs2[16][68];
    int tid = threadIdx.x;
    int tx = tid & 15, ty = tid >> 4;
    int m0 = blockIdx.y * 64, n0 = blockIdx.x * 64;
    float acc1[4][4] = {};
    float acc2[4][4] = {};

    for (int kb = 0; kb < 256; kb += 16) {
        {   // A tile [64 x 16] -> As[k][m]
            int m = tid >> 2, kq = tid & 3;
            float4 a4 = *(const float4*)(A + (size_t)(m0 + m) * 256 + kb + kq * 4);
            As[kq * 4 + 0][m] = a4.x; As[kq * 4 + 1][m] = a4.y;
            As[kq * 4 + 2][m] = a4.z; As[kq * 4 + 3][m] = a4.w;
        }
        {   // W tile: Bs1[k][n]
            int k = tid >> 4, nq = tid & 15;
            *(float4*)&Bs1[k][nq * 4] =
                *(const float4*)(W + (size_t)(kb + k) * CF + n0 + nq * 4);
        }
        {   // P tile (transposed stage): Bs2[k][n] = P[n][k]
            int n = tid >> 2, kq = tid & 3;
            float4 b4 = *(const float4*)(P + (size_t)(n0 + n) * 256 + kb + kq * 4);
            Bs2[kq * 4 + 0][n] = b4.x; Bs2[kq * 4 + 1][n] = b4.y;
            Bs2[kq * 4 + 2][n] = b4.z; Bs2[kq * 4 + 3][n] = b4.w;
        }
        __syncthreads();
        #pragma unroll
        for (int k = 0; k < 16; ++k) {
            float4 ra  = *(const float4*)&As[k][ty * 4];
            float4 rb1 = *(const float4*)&Bs1[k][tx * 4];
            float4 rb2 = *(const float4*)&Bs2[k][tx * 4];
            float a[4] = {ra.x, ra.y, ra.z, ra.w};
            float b1[4] = {rb1.x, rb1.y, rb1.z, rb1.w};
            float b2[4] = {rb2.x, rb2.y, rb2.z, rb2.w};
            #pragma unroll
            for (int ii = 0; ii < 4; ++ii)
                #pragma unroll
                for (int jj = 0; jj < 4; ++jj) {
                    acc1[ii][jj] += a[ii] * b1[jj];
                    acc2[ii][jj] += a[ii] * b2[jj];
                }
        }
        __syncthreads();
    }

    #pragma unroll
    for (int ii = 0; ii < 4; ++ii) {
        int row = m0 + ty * 4 + ii;
        #pragma unroll
        for (int jj = 0; jj < 4; ++jj) {
            int col = n0 + tx * 4 + jj;
            float v = acc1[ii][jj];
            g_support[(size_t)row * CF + col] = v;
            g_support_bf[(size_t)row * CF + col] = __float2bfloat16(v);
            C[(size_t)row * CF + col] = acc2[ii][jj] + bias1[col] + bias2[col];
        }
    }
}

// ------------- per-node head scalars: exponentials only ---------------------
__global__ __launch_bounds__(256) void stats_kernel(
    const float* __restrict__ wu, const float* __restrict__ wv)
{
    int t = blockIdx.x * blockDim.x + threadIdx.x;   // 0 .. 32767
    int n = t >> 2, h = t & 3;
    const float* srow = g_support + (size_t)n * CF + h * 64;
    float s1 = 0.f, s2 = 0.f;
    #pragma unroll 8
    for (int o = 0; o < 64; ++o) {
        float sv = srow[o];
        s1 += sv * wu[h * 64 + o];
        s2 += sv * wv[h * 64 + o];
    }
    g_statJ[n * NHEADS + h] = make_float2(__expf(s1), __expf(0.2f * s1));
    g_statI[n * NHEADS + h] = make_float2(__expf(s2), __expf(0.2f * s2));
}

// -------------------------- sparse attention (partial) ---------------------
// grid (128, 8): blockIdx.x = i-block (64 rows), blockIdx.y = j-chunk (1024 j)
// 512 thr = 16 warps; warp w owns rows w*4..w*4+3; lane owns cols lane*8..+7.
// 3-buffer bulk-TMA pipeline with 64-row tiles; inner body runs two 32-j
// ballot groups sequentially, reusing the SAME av[4]/m[4] registers (keeps
// the measured 61-reg R11 hot-loop footprint while halving sync events).
__global__ __launch_bounds__(ATHREADS, 2) void attn_partial(
    const float* __restrict__ adj)
{
    extern __shared__ char smraw[];
    __nv_bfloat16* sS = (__nv_bfloat16*)smraw;                   // [3][64][256] bf16
    float2* sstat = (float2*)(smraw + NBUF * TILE_BYTES);        // [3][64][4]
    __shared__ unsigned long long mbars[NBUF];

    int tid = threadIdx.x, warp = tid >> 5, lane = tid & 31;
    int i0 = blockIdx.x * RPB;
    int chunk = blockIdx.y;
    int j0 = chunk * JCHUNK;
    int h = lane >> 3;
    int ibase = i0 + warp * 4;

    if (tid == 0) {
        #pragma unroll
        for (int b = 0; b < NBUF; ++b)
            asm volatile("mbarrier.init.shared.b64 [%0], 1;"
                         :: "r"(smem_u32(&mbars[b])) : "memory");
    }
    __syncthreads();

    auto issue_tile = [&](int t, int b) {   // tid==0 only
        unsigned mb = smem_u32(&mbars[b]);
        asm volatile("mbarrier.arrive.expect_tx.shared.b64 _, [%0], %1;"
                     :: "r"(mb), "r"(TILE_BYTES + STAT_BYTES) : "memory");
        const char* srcS = (const char*)(g_support_bf + (size_t)(j0 + t * JTILE) * CF);
        unsigned dstS = smem_u32(sS + (size_t)b * JTILE * CF);
        asm volatile(
            "cp.async.bulk.shared::cta.global.mbarrier::complete_tx::bytes "
            "[%0], [%1], %2, [%3];"
            :: "r"(dstS), "l"(srcS), "r"(TILE_BYTES), "r"(mb) : "memory");
        const char* srcT = (const char*)(g_statJ + (size_t)(j0 + t * JTILE) * NHEADS);
        unsigned dstT = smem_u32(sstat + b * JTILE * NHEADS);
        asm volatile(
            "cp.async.bulk.shared::cta.global.mbarrier::complete_tx::bytes "
            "[%0], [%1], %2, [%3];"
            :: "r"(dstT), "l"(srcT), "r"(STAT_BYTES), "r"(mb) : "memory");
    };

    float br[4], b5r[4];
    #pragma unroll
    for (int rr = 0; rr < 4; ++rr) {
        float2 si = g_statI[(size_t)(ibase + rr) * NHEADS + h];
        br[rr] = si.x; b5r[rr] = si.y;
    }

    unsigned long long accp[4][4] = {};   // packed f32x2 accumulators
    float den[4] = {0.f, 0.f, 0.f, 0.f};

    // av[4] always holds the NEXT 32-j group's adj values (one group only).
    float av[4];
    #pragma unroll
    for (int rr = 0; rr < 4; ++rr)
        av[rr] = adj[(size_t)(ibase + rr) * NN + j0 + lane];

    if (tid == 0) {
        issue_tile(0, 0);
        issue_tile(1, 1);
        issue_tile(2, 2);
    }

    int b = 0, par = 0;
    for (int jt = 0; jt < NT; ++jt) {
        // wait for 64-row tile jt (acquire orders LDS after TMA writes)
        mbar_wait(smem_u32(&mbars[b]), (unsigned)par);

        const __nv_bfloat16* tile = sS + (size_t)b * JTILE * CF;
        const float2* stt = sstat + b * JTILE * NHEADS;

        #pragma unroll
        for (int g = 0; g < 2; ++g) {
            unsigned m[4];
            #pragma unroll
            for (int rr = 0; rr < 4; ++rr)
                m[rr] = __ballot_sync(0xffffffffu, av[rr] != 0.0f);

            // prefetch next 32-j group's adj (same registers, single group)
            int goff = jt * JTILE + (g + 1) * 32;
            if (goff < JCHUNK) {
                #pragma unroll
                for (int rr = 0; rr < 4; ++rr)
                    av[rr] = adj[(size_t)(ibase + rr) * NN + j0 + goff + lane];
            }

            const __nv_bfloat16* tg = tile + (size_t)g * 32 * CF;
            const float2* sg = stt + g * 32 * NHEADS;

            #pragma unroll
            for (int rr = 0; rr < 4; ++rr) {
                unsigned mask = m[rr];
                while (mask) {
                    int j = __ffs(mask) - 1;
                    mask &= mask - 1;
                    float2 st = sg[j * NHEADS + h];         // {e^f1, e^.2f1}
                    // exp(leaky_relu(f1+f2)) == max(e^f1 e^f2, e^.2f1 e^.2f2)
                    float e = fmaxf(st.x * br[rr], st.y * b5r[rr]);
                    den[rr] += e;
                    uint4 v = *(const uint4*)(tg + (size_t)j * CF + (lane << 3));
                    unsigned long long e2, p;
                    asm("mov.b64 %0, {%1, %1};" : "=l"(e2) : "f"(e));
                    asm("mov.b64 %0, {%1, %2};" : "=l"(p)
                        : "r"(v.x << 16), "r"(v.x & 0xffff0000u));
                    asm("fma.rn.f32x2 %0, %1, %2, %0;" : "+l"(accp[rr][0]) : "l"(p), "l"(e2));
                    asm("mov.b64 %0, {%1, %2};" : "=l"(p)
                        : "r"(v.y << 16), "r"(v.y & 0xffff0000u));
                    asm("fma.rn.f32x2 %0, %1, %2, %0;" : "+l"(accp[rr][1]) : "l"(p), "l"(e2));
                    asm("mov.b64 %0, {%1, %2};" : "=l"(p)
                        : "r"(v.z << 16), "r"(v.z & 0xffff0000u));
                    asm("fma.rn.f32x2 %0, %1, %2, %0;" : "+l"(accp[rr][2]) : "l"(p), "l"(e2));
                    asm("mov.b64 %0, {%1, %2};" : "=l"(p)
                        : "r"(v.w << 16), "r"(v.w & 0xffff0000u));
                    asm("fma.rn.f32x2 %0, %1, %2, %0;" : "+l"(accp[rr][3]) : "l"(p), "l"(e2));
                }
            }
        }

        __syncthreads();   // all warps done with tile jt; buffer b reusable
        if (tid == 0 && jt + 3 < NT) issue_tile(jt + 3, b);
        if (++b == NBUF) { b = 0; par ^= 1; }
    }

    // write partials
    #pragma unroll
    for (int rr = 0; rr < 4; ++rr) {
        int i = ibase + rr;
        float o[8];
        #pragma unroll
        for (int k = 0; k < 4; ++k) {
            unsigned lo, hi;
            asm("mov.b64 {%0, %1}, %2;" : "=r"(lo), "=r"(hi) : "l"(accp[rr][k]));
            o[k * 2]     = __uint_as_float(lo);
            o[k * 2 + 1] = __uint_as_float(hi);
        }
        float* pn = g_pnum + ((size_t)chunk * NN + i) * CF + (lane << 3);
        *(float4*)pn       = make_float4(o[0], o[1], o[2], o[3]);
        *(float4*)(pn + 4) = make_float4(o[4], o[5], o[6], o[7]);
        if ((lane & 7) == 0)
            g_pden[((size_t)chunk * NN + i) * NHEADS + h] = den[rr];
    }
}

// -------------------- combine partials: out += num/den ---------------------
__global__ __launch_bounds__(256) void combine_kernel(float* __restrict__ out)
{
    int i = blockIdx.x;
    int c = threadIdx.x;
    int h = c >> 6;
    float s = 0.f, d = 0.f;
    #pragma unroll
    for (int k = 0; k < CHUNKS; ++k) {
        s += g_pnum[((size_t)k * NN + i) * CF + c];
        d += g_pden[((size_t)k * NN + i) * NHEADS + h];
    }
    out[(size_t)i * CF + c] += s / d;
}

// ------------------------------- launch ------------------------------------
extern "C" void kernel_launch(void* const* d_in, const int* in_sizes, int n_in,
                              void* d_out, int out_size)
{
    const float* inputs = (const float*)d_in[0];
    const float* adj    = (const float*)d_in[1];
    const float* weight = (const float*)d_in[2];
    const float* wu     = (const float*)d_in[3];
    const float* wv     = (const float*)d_in[4];
    const float* bias   = (const float*)d_in[5];
    const float* projw  = (const float*)d_in[6];
    const float* projb  = (const float*)d_in[7];
    float* out = (float*)d_out;

    const int ASMEM = NBUF * TILE_BYTES + NBUF * STAT_BYTES;  // 104448
    cudaFuncSetAttribute(attn_partial,
                         cudaFuncAttributeMaxDynamicSharedMemorySize, ASMEM);

    dim3 gemm_grid(CF / 64, NN / 64);   // (4, 128)

    // support = inputs @ weight (+bf16 copy); out = inputs @ proj_w.T + biases
    dual_gemm_kernel<<<gemm_grid, 256>>>(inputs, weight, projw, out,
                                         bias, projb);
    // per-node head scalars + exponentials
    stats_kernel<<<NN * NHEADS / 256, 256>>>(wu, wv);
    // partial attention over j-chunks
    attn_partial<<<dim3(NN / RPB, CHUNKS), ATHREADS, ASMEM>>>(adj);
    // out += num/den
    combine_kernel<<<NN, 256>>>(out);
}